// round 4
// baseline (speedup 1.0000x reference)
#include <cuda_runtime.h>
#include <cstdint>

#define N_MAX 100000
#define D 64
#define D4 16               // D/4 float4 per row
#define TILE_ROWS 128
#define SCAN_B 1024

// Scratch (static device globals — no allocations allowed)
__device__ int    g_deg     [N_MAX];
__device__ int    g_rowptr  [N_MAX + 1];
__device__ int    g_cursor  [N_MAX];
__device__ int    g_srcsort [1000000];
__device__ int    g_bsums   [128];
__device__ float  s_dinv    [N_MAX];
__device__ float4 s_g       [N_MAX * D4];   // dinv-scaled features (gather source)
__device__ float4 s_y       [N_MAX * D4];   // layer-1 output

// ---------------------------------------------------------------------------
__global__ void zero_deg_kernel(int n) {
    int i = blockIdx.x * blockDim.x + threadIdx.x;
    if (i < n) g_deg[i] = 0;
}

// NOTE: edge_index is INT32 on device (JAX x64 disabled canonicalizes int64->int32).
__global__ void hist_kernel(const int* __restrict__ ei, int E) {
    int e = blockIdx.x * blockDim.x + threadIdx.x;
    if (e < E) atomicAdd(&g_deg[ei[E + e]], 1);
}

// exclusive scan, stage 1: per-block scan + block totals
__global__ __launch_bounds__(SCAN_B) void scan_local_kernel(int n) {
    __shared__ int sh[SCAN_B];
    int i = blockIdx.x * SCAN_B + threadIdx.x;
    int v = (i < n) ? g_deg[i] : 0;
    sh[threadIdx.x] = v;
    __syncthreads();
    #pragma unroll
    for (int off = 1; off < SCAN_B; off <<= 1) {
        int t = (threadIdx.x >= off) ? sh[threadIdx.x - off] : 0;
        __syncthreads();
        sh[threadIdx.x] += t;
        __syncthreads();
    }
    if (i < n) g_rowptr[i] = sh[threadIdx.x] - v;     // block-local exclusive
    if (threadIdx.x == SCAN_B - 1) g_bsums[blockIdx.x] = sh[SCAN_B - 1];
}

// stage 2: scan the (<=128) block totals in one block
__global__ __launch_bounds__(128) void scan_bsums_kernel(int nb) {
    __shared__ int sh[128];
    int t = threadIdx.x;
    int v = (t < nb) ? g_bsums[t] : 0;
    sh[t] = v;
    __syncthreads();
    #pragma unroll
    for (int off = 1; off < 128; off <<= 1) {
        int u = (t >= off) ? sh[t - off] : 0;
        __syncthreads();
        sh[t] += u;
        __syncthreads();
    }
    if (t < nb) g_bsums[t] = sh[t] - v;               // exclusive
}

// stage 3: add block offsets, init cursors, set rowptr[n] = E
__global__ __launch_bounds__(SCAN_B) void scan_add_kernel(int n, int E) {
    int i = blockIdx.x * SCAN_B + threadIdx.x;
    if (i < n) {
        int r = g_rowptr[i] + g_bsums[blockIdx.x];
        g_rowptr[i] = r;
        g_cursor[i] = r;
    }
    if (i == 0) g_rowptr[n] = E;
}

__global__ void dinv_kernel(int n) {
    int i = blockIdx.x * blockDim.x + threadIdx.x;
    if (i < n) s_dinv[i] = rsqrtf((float)g_deg[i] + 1.0f);   // +1 self loop
}

// counting-sort scatter of src ids into dst-contiguous segments
__global__ void sort_kernel(const int* __restrict__ ei, int E) {
    int e = blockIdx.x * blockDim.x + threadIdx.x;
    if (e < E) {
        int src = ei[e];
        int dst = ei[E + e];
        int pos = atomicAdd(&g_cursor[dst], 1);
        g_srcsort[pos] = src;
    }
}

// ---------------------------------------------------------------------------
// h = X @ W ;  g = dinv[row] * h
// Block: 256 threads, 128 rows. Thread = 8 rows x 4 cols.
__global__ __launch_bounds__(256) void gemm_scale_kernel(
    const float* __restrict__ X, const float* __restrict__ W, int n)
{
    __shared__ float4 ws[D * D4];          // W: 64x64
    __shared__ float4 xs[TILE_ROWS * D4];  // X tile

    const int tid  = threadIdx.x;
    const int row0 = blockIdx.x * TILE_ROWS;

    const float4* W4 = (const float4*)W;
    #pragma unroll
    for (int i = tid; i < D * D4; i += 256) ws[i] = W4[i];

    const float4* X4 = (const float4*)X;
    #pragma unroll
    for (int i = tid; i < TILE_ROWS * D4; i += 256) {
        int rr = i >> 4;
        float4 v = make_float4(0.f, 0.f, 0.f, 0.f);
        if (row0 + rr < n) v = X4[(size_t)(row0 + rr) * D4 + (i & 15)];
        xs[i] = v;
    }
    __syncthreads();

    const int cg = tid & 15;   // col group: cols cg*4..cg*4+3
    const int rg = tid >> 4;   // row group: rows rg*8..rg*8+7

    float acc[8][4];
    #pragma unroll
    for (int r = 0; r < 8; r++)
        #pragma unroll
        for (int c = 0; c < 4; c++) acc[r][c] = 0.f;

    #pragma unroll 2
    for (int k = 0; k < D; k += 4) {
        float4 w0 = ws[(k + 0) * D4 + cg];
        float4 w1 = ws[(k + 1) * D4 + cg];
        float4 w2 = ws[(k + 2) * D4 + cg];
        float4 w3 = ws[(k + 3) * D4 + cg];
        #pragma unroll
        for (int r = 0; r < 8; r++) {
            float4 xv = xs[(rg * 8 + r) * D4 + (k >> 2)];
            acc[r][0] += xv.x * w0.x + xv.y * w1.x + xv.z * w2.x + xv.w * w3.x;
            acc[r][1] += xv.x * w0.y + xv.y * w1.y + xv.z * w2.y + xv.w * w3.y;
            acc[r][2] += xv.x * w0.z + xv.y * w1.z + xv.z * w2.z + xv.w * w3.z;
            acc[r][3] += xv.x * w0.w + xv.y * w1.w + xv.z * w2.w + xv.w * w3.w;
        }
    }

    #pragma unroll
    for (int r = 0; r < 8; r++) {
        int row = row0 + rg * 8 + r;
        if (row < n) {
            float dv = s_dinv[row];
            s_g[(size_t)row * D4 + cg] =
                make_float4(acc[r][0] * dv, acc[r][1] * dv,
                            acc[r][2] * dv, acc[r][3] * dv);
        }
    }
}

// ---------------------------------------------------------------------------
// Gather-aggregate + epilogue:  out[v] = relu(dinv[v] * (g[v] + sum g[src]) + b)
// 16 threads per node, one float4 column each.
__global__ __launch_bounds__(256) void aggregate_kernel(
    const float* __restrict__ b, float* __restrict__ out, int n)
{
    int idx = blockIdx.x * blockDim.x + threadIdx.x;
    int v = idx >> 4;
    if (v >= n) return;
    int j = idx & 15;

    float4 acc = s_g[(size_t)v * D4 + j];              // self loop
    int beg = g_rowptr[v];
    int end = g_rowptr[v + 1];
    for (int k = beg; k < end; k++) {
        int s = g_srcsort[k];                          // broadcast within half-warp
        float4 gg = s_g[(size_t)s * D4 + j];
        acc.x += gg.x; acc.y += gg.y; acc.z += gg.z; acc.w += gg.w;
    }

    float dv = s_dinv[v];
    float4 bb = ((const float4*)b)[j];
    float4 o;
    o.x = fmaxf(fmaf(acc.x, dv, bb.x), 0.f);
    o.y = fmaxf(fmaf(acc.y, dv, bb.y), 0.f);
    o.z = fmaxf(fmaf(acc.z, dv, bb.z), 0.f);
    o.w = fmaxf(fmaf(acc.w, dv, bb.w), 0.f);
    ((float4*)out)[(size_t)v * D4 + j] = o;
}

// ---------------------------------------------------------------------------
extern "C" void kernel_launch(void* const* d_in, const int* in_sizes, int n_in,
                              void* d_out, int out_size)
{
    const float* x  = (const float*)d_in[0];
    const int*   ei = (const int*)d_in[1];      // int32! (JAX x64 disabled)
    const float* W1 = (const float*)d_in[2];
    const float* b1 = (const float*)d_in[3];
    const float* W2 = (const float*)d_in[4];
    const float* b2 = (const float*)d_in[5];
    float* out = (float*)d_out;

    const int n = in_sizes[0] / D;        // 100000
    const int E = in_sizes[1] / 2;        // 1000000

    const int nb_n   = (n + 255) / 256;
    const int nb_e   = (E + 255) / 256;
    const int nb_sc  = (n + SCAN_B - 1) / SCAN_B;
    const int nb_gmm = (n + TILE_ROWS - 1) / TILE_ROWS;
    const int nb_agg = (n * D4 + 255) / 256;

    // --- graph preprocessing (shared by both layers) ---
    zero_deg_kernel<<<nb_n, 256>>>(n);
    hist_kernel<<<nb_e, 256>>>(ei, E);
    scan_local_kernel<<<nb_sc, SCAN_B>>>(n);
    scan_bsums_kernel<<<1, 128>>>(nb_sc);
    scan_add_kernel<<<nb_sc, SCAN_B>>>(n, E);
    dinv_kernel<<<nb_n, 256>>>(n);
    sort_kernel<<<nb_e, 256>>>(ei, E);

    float* y = nullptr;
    cudaGetSymbolAddress((void**)&y, s_y);

    // layer 1
    gemm_scale_kernel<<<nb_gmm, 256>>>(x, W1, n);
    aggregate_kernel<<<nb_agg, 256>>>(b1, y, n);

    // layer 2
    gemm_scale_kernel<<<nb_gmm, 256>>>(y, W2, n);
    aggregate_kernel<<<nb_agg, 256>>>(b2, out, n);
}

// round 5
// speedup vs baseline: 1.0810x; 1.0810x over previous
#include <cuda_runtime.h>
#include <cstdint>

#define N_MAX 100000
#define D 64
#define D4 16               // D/4 float4 per row
#define TILE_ROWS 128
#define SCAN_B 1024

// Scratch (static device globals — no allocations allowed)
__device__ int    g_deg     [N_MAX];
__device__ int    g_rowptr  [N_MAX + 1];
__device__ int    g_cursor  [N_MAX];
__device__ int    g_srcsort [1000000];
__device__ int    g_bsums   [128];
__device__ float  s_dinv    [N_MAX];
__device__ float4 s_g       [N_MAX * D4];   // dinv-scaled features (gather source)
__device__ float4 s_y       [N_MAX * D4];   // layer-1 output

// ---------------------------------------------------------------------------
__global__ void zero_deg_kernel(int n) {
    int i = blockIdx.x * blockDim.x + threadIdx.x;
    if (i < n) g_deg[i] = 0;
}

// edge_index is INT32 on device (JAX x64 disabled canonicalizes int64->int32).
__global__ void hist_kernel(const int* __restrict__ ei, int E) {
    int e = blockIdx.x * blockDim.x + threadIdx.x;
    if (e < E) atomicAdd(&g_deg[ei[E + e]], 1);
}

// exclusive scan, stage 1: per-block scan + block totals
__global__ __launch_bounds__(SCAN_B) void scan_local_kernel(int n) {
    __shared__ int sh[SCAN_B];
    int i = blockIdx.x * SCAN_B + threadIdx.x;
    int v = (i < n) ? g_deg[i] : 0;
    sh[threadIdx.x] = v;
    __syncthreads();
    #pragma unroll
    for (int off = 1; off < SCAN_B; off <<= 1) {
        int t = (threadIdx.x >= off) ? sh[threadIdx.x - off] : 0;
        __syncthreads();
        sh[threadIdx.x] += t;
        __syncthreads();
    }
    if (i < n) g_rowptr[i] = sh[threadIdx.x] - v;     // block-local exclusive
    if (threadIdx.x == SCAN_B - 1) g_bsums[blockIdx.x] = sh[SCAN_B - 1];
}

// stage 2 (fused): every block redundantly reduces the block sums below its
// blockIdx to get its offset; also computes dinv and inits cursors.
__global__ __launch_bounds__(SCAN_B) void scan_add_fused_kernel(int n, int E, int nb) {
    __shared__ int sh[128];
    __shared__ int offset;
    int t = threadIdx.x;
    if (t < 128) sh[t] = (t < nb && t < (int)blockIdx.x) ? g_bsums[t] : 0;
    __syncthreads();
    if (t < 64) sh[t] += sh[t + 64];
    __syncthreads();
    if (t < 32) {
        int v = sh[t] + sh[t + 32];
        #pragma unroll
        for (int o = 16; o > 0; o >>= 1) v += __shfl_down_sync(0xffffffffu, v, o);
        if (t == 0) offset = v;
    }
    __syncthreads();
    int i = blockIdx.x * SCAN_B + t;
    if (i < n) {
        int r = g_rowptr[i] + offset;
        g_rowptr[i] = r;
        g_cursor[i] = r;
        s_dinv[i] = rsqrtf((float)g_deg[i] + 1.0f);   // +1 self loop
    }
    if (i == 0) g_rowptr[n] = E;
}

// counting-sort scatter of src ids into dst-contiguous segments
__global__ void sort_kernel(const int* __restrict__ ei, int E) {
    int e = blockIdx.x * blockDim.x + threadIdx.x;
    if (e < E) {
        int src = ei[e];
        int dst = ei[E + e];
        int pos = atomicAdd(&g_cursor[dst], 1);
        g_srcsort[pos] = src;
    }
}

// ---------------------------------------------------------------------------
// h = X @ W ;  g = dinv[row] * h
// Block: 256 threads, 128 rows. Thread = 8 rows x 4 cols.
__global__ __launch_bounds__(256) void gemm_scale_kernel(
    const float* __restrict__ X, const float* __restrict__ W, int n)
{
    __shared__ float4 ws[D * D4];          // W: 64x64
    __shared__ float4 xs[TILE_ROWS * D4];  // X tile

    const int tid  = threadIdx.x;
    const int row0 = blockIdx.x * TILE_ROWS;

    const float4* W4 = (const float4*)W;
    #pragma unroll
    for (int i = tid; i < D * D4; i += 256) ws[i] = W4[i];

    const float4* X4 = (const float4*)X;
    #pragma unroll
    for (int i = tid; i < TILE_ROWS * D4; i += 256) {
        int rr = i >> 4;
        float4 v = make_float4(0.f, 0.f, 0.f, 0.f);
        if (row0 + rr < n) v = X4[(size_t)(row0 + rr) * D4 + (i & 15)];
        xs[i] = v;
    }
    __syncthreads();

    const int cg = tid & 15;   // col group: cols cg*4..cg*4+3
    const int rg = tid >> 4;   // row group: rows rg*8..rg*8+7

    float acc[8][4];
    #pragma unroll
    for (int r = 0; r < 8; r++)
        #pragma unroll
        for (int c = 0; c < 4; c++) acc[r][c] = 0.f;

    #pragma unroll 2
    for (int k = 0; k < D; k += 4) {
        float4 w0 = ws[(k + 0) * D4 + cg];
        float4 w1 = ws[(k + 1) * D4 + cg];
        float4 w2 = ws[(k + 2) * D4 + cg];
        float4 w3 = ws[(k + 3) * D4 + cg];
        #pragma unroll
        for (int r = 0; r < 8; r++) {
            float4 xv = xs[(rg * 8 + r) * D4 + (k >> 2)];
            acc[r][0] += xv.x * w0.x + xv.y * w1.x + xv.z * w2.x + xv.w * w3.x;
            acc[r][1] += xv.x * w0.y + xv.y * w1.y + xv.z * w2.y + xv.w * w3.y;
            acc[r][2] += xv.x * w0.z + xv.y * w1.z + xv.z * w2.z + xv.w * w3.z;
            acc[r][3] += xv.x * w0.w + xv.y * w1.w + xv.z * w2.w + xv.w * w3.w;
        }
    }

    #pragma unroll
    for (int r = 0; r < 8; r++) {
        int row = row0 + rg * 8 + r;
        if (row < n) {
            float dv = s_dinv[row];
            s_g[row * D4 + cg] =
                make_float4(acc[r][0] * dv, acc[r][1] * dv,
                            acc[r][2] * dv, acc[r][3] * dv);
        }
    }
}

// ---------------------------------------------------------------------------
// Gather-aggregate + epilogue:  out[v] = relu(dinv[v] * (g[v] + sum g[src]) + b)
// 16 threads per node, one float4 column each. Unroll x4 for MLP.
__global__ __launch_bounds__(256) void aggregate_kernel(
    const float* __restrict__ b, float* __restrict__ out, int n)
{
    int idx = blockIdx.x * blockDim.x + threadIdx.x;
    int v = idx >> 4;
    if (v >= n) return;
    int j = idx & 15;

    float4 acc = __ldg(&s_g[v * D4 + j]);              // self loop
    int beg = __ldg(&g_rowptr[v]);
    int end = __ldg(&g_rowptr[v + 1]);

    int k = beg;
    #pragma unroll 1
    for (; k + 4 <= end; k += 4) {
        int s0 = __ldg(&g_srcsort[k + 0]);
        int s1 = __ldg(&g_srcsort[k + 1]);
        int s2 = __ldg(&g_srcsort[k + 2]);
        int s3 = __ldg(&g_srcsort[k + 3]);
        float4 a0 = __ldg(&s_g[s0 * D4 + j]);
        float4 a1 = __ldg(&s_g[s1 * D4 + j]);
        float4 a2 = __ldg(&s_g[s2 * D4 + j]);
        float4 a3 = __ldg(&s_g[s3 * D4 + j]);
        acc.x += (a0.x + a1.x) + (a2.x + a3.x);
        acc.y += (a0.y + a1.y) + (a2.y + a3.y);
        acc.z += (a0.z + a1.z) + (a2.z + a3.z);
        acc.w += (a0.w + a1.w) + (a2.w + a3.w);
    }
    for (; k < end; k++) {
        int s = __ldg(&g_srcsort[k]);
        float4 a = __ldg(&s_g[s * D4 + j]);
        acc.x += a.x; acc.y += a.y; acc.z += a.z; acc.w += a.w;
    }

    float dv = __ldg(&s_dinv[v]);
    float4 bb = __ldg(&((const float4*)b)[j]);
    float4 o;
    o.x = fmaxf(fmaf(acc.x, dv, bb.x), 0.f);
    o.y = fmaxf(fmaf(acc.y, dv, bb.y), 0.f);
    o.z = fmaxf(fmaf(acc.z, dv, bb.z), 0.f);
    o.w = fmaxf(fmaf(acc.w, dv, bb.w), 0.f);
    ((float4*)out)[v * D4 + j] = o;
}

// ---------------------------------------------------------------------------
extern "C" void kernel_launch(void* const* d_in, const int* in_sizes, int n_in,
                              void* d_out, int out_size)
{
    const float* x  = (const float*)d_in[0];
    const int*   ei = (const int*)d_in[1];      // int32 (JAX x64 disabled)
    const float* W1 = (const float*)d_in[2];
    const float* b1 = (const float*)d_in[3];
    const float* W2 = (const float*)d_in[4];
    const float* b2 = (const float*)d_in[5];
    float* out = (float*)d_out;

    const int n = in_sizes[0] / D;        // 100000
    const int E = in_sizes[1] / 2;        // 1000000

    const int nb_n   = (n + 255) / 256;
    const int nb_e   = (E + 255) / 256;
    const int nb_sc  = (n + SCAN_B - 1) / SCAN_B;
    const int nb_gmm = (n + TILE_ROWS - 1) / TILE_ROWS;
    const int nb_agg = (n * D4 + 255) / 256;

    // --- graph preprocessing (shared by both layers) ---
    zero_deg_kernel<<<nb_n, 256>>>(n);
    hist_kernel<<<nb_e, 256>>>(ei, E);
    scan_local_kernel<<<nb_sc, SCAN_B>>>(n);
    scan_add_fused_kernel<<<nb_sc, SCAN_B>>>(n, E, nb_sc);
    sort_kernel<<<nb_e, 256>>>(ei, E);

    float* y = nullptr;
    cudaGetSymbolAddress((void**)&y, s_y);

    // layer 1
    gemm_scale_kernel<<<nb_gmm, 256>>>(x, W1, n);
    aggregate_kernel<<<nb_agg, 256>>>(b1, y, n);

    // layer 2
    gemm_scale_kernel<<<nb_gmm, 256>>>(y, W2, n);
    aggregate_kernel<<<nb_agg, 256>>>(b2, out, n);
}